// round 17
// baseline (speedup 1.0000x reference)
#include <cuda_runtime.h>

#define HH 1024
#define WW 1024
#define MM 512            // 16 segments * 32 samples
#define TW 16.0f          // window half-width used only for bucketing
#define BCAP 96           // max edges per 128-px bucket
#define NT 256

__global__ __launch_bounds__(NT)
void bvr_fused_kernel(const float* __restrict__ cp,
                      const float* __restrict__ color,
                      float* __restrict__ out)
{
    __shared__ float4 s_cf[17][2];      // Horner coeffs per segment (+ final joint)
    __shared__ float2 s_pts[MM + 2];    // sampled path points (+wrap pad)
    __shared__ float2 s_bk[9][BCAP];    // bucket lists: {w/2, xc/2}
    __shared__ int    s_bcnt[9];
    __shared__ float  s_btot[9];

    const int tid = threadIdx.x;
    const int y   = blockIdx.x;
    const float fy = (float)y;

    // hoisted color loads (latency hidden behind phases 0-2)
    const float cr = __ldg(color + 0);
    const float cg = __ldg(color + 1);
    const float cb = __ldg(color + 2);

    if (tid < 9) { s_bcnt[tid] = 0; s_btot[tid] = 0.0f; }

    // ---- 0. Per-segment Horner coefficients (threads 0..16) ----
    if (tid < 17) {
        const float* p = cp + 6 * tid;
        float p0x = p[0], p0y = p[1];
        if (tid < 16) {
            float p1x = p[2], p1y = p[3];
            float p2x = p[4], p2y = p[5];
            float p3x = p[6], p3y = p[7];
            s_cf[tid][0] = make_float4(p0x, 3.f * (p1x - p0x),
                                       3.f * (p2x - 2.f * p1x + p0x),
                                       p3x - 3.f * p2x + 3.f * p1x - p0x);
            s_cf[tid][1] = make_float4(p0y, 3.f * (p1y - p0y),
                                       3.f * (p2y - 2.f * p1y + p0y),
                                       p3y - 3.f * p2y + 3.f * p1y - p0y);
        } else {
            // joint entry: c0 = last control point (exact), used by i=511 @ t=0
            s_cf[16][0] = make_float4(p0x, 0.f, 0.f, 0.f);
            s_cf[16][1] = make_float4(p0y, 0.f, 0.f, 0.f);
        }
    }
    __syncthreads();

    // ---- 1. Sample path: Horner, 2 points per thread ----
    // j==31 maps to next segment @ t=0 -> joint points are bit-identical to
    // the shared control point (keeps joint edges at dy == 0 exactly).
    #pragma unroll
    for (int it = 0; it < 2; ++it) {
        int i = tid + it * NT;
        int s = i >> 5;
        int j = i & 31;
        int s2 = s + ((j + 1) >> 5);            // j==31 -> s+1
        float t = (j < 31) ? (float)j * (1.0f / 31.0f) : 0.0f;
        float4 cx = s_cf[s2][0];
        float4 cy = s_cf[s2][1];
        float px = fmaf(fmaf(fmaf(cx.w, t, cx.z), t, cx.y), t, cx.x);
        float py = fmaf(fmaf(fmaf(cy.w, t, cy.z), t, cy.y), t, cy.x);
        float2 pt = make_float2(px, py);
        s_pts[i] = pt;
        if (i == 0) s_pts[MM] = pt;             // wrap point for edge 511
    }
    __syncthreads();

    // ---- 2. Compact edge pair (2t, 2t+1) into 128-px buckets ----
    {
        const int e0 = tid * 2;
        float4 pp = *(const float4*)&s_pts[e0];     // points e0, e0+1 (LDS.128)
        float2 p2 = s_pts[e0 + 2];                  // point e0+2 (LDS.64)
        float2 eP0[2] = { make_float2(pp.x, pp.y), make_float2(pp.z, pp.w) };
        float2 eP1[2] = { make_float2(pp.z, pp.w), p2 };

        #pragma unroll
        for (int h = 0; h < 2; ++h) {
            float2 p0 = eP0[h];
            float2 p1 = eP1[h];
            float dy = p1.y - p0.y;
            if (fabsf(dy) < 1e-6f) continue;        // coeff == 0 in reference

            float ba = p0.y - 1.2f * dy;            // |w|>1e-10 needs t in [-1.2,2.2]
            float bb = p0.y + 2.2f * dy;
            if (fy < fminf(ba, bb) || fy > fmaxf(ba, bb)) continue;

            float t = __fdividef(fy - p0.y, dy + 1e-8f);
            // v1*v2 = 1 / (1 + e^-20t + e^(20t-20) + e^-20)  (exact expansion)
            float ea = __expf(-20.0f * t);
            float eb = __expf(20.0f * (t - 1.0f));
            float denom = 1.0f + ea + eb + 2.0611537e-9f;
            if (denom > 1e10f) continue;            // |w| < 1e-10

            float coeff = (dy > 0.0f) ? 1.0f : -1.0f;
            float w  = __fdividef(coeff, denom);
            float xc = p0.x + t * (p1.x - p0.x);
            if (xc < -TW) continue;                 // sigma ~0 across whole row

            int xlo = (int)ceilf(xc - TW);
            xlo = max(0, min(xlo, WW));
            int bkt = min(xlo >> 7, 8);             // 0..7 bands, 8 = right of row

            int slot = atomicAdd(&s_bcnt[bkt], 1);
            s_bk[bkt][slot] = make_float2(0.5f * w, 0.5f * xc);
            atomicAdd(&s_btot[bkt], w);
        }
    }
    __syncthreads();

    // ---- 3. Direct evaluation: suffix buckets (full w) + nearby buckets ----
    const int wrp = tid >> 5;                       // warp covers px [wrp*128,+128)
    const float hbf = 0.5f * (float)(tid * 4);      // half of first pixel coord

    float wbase = 0.0f;
    #pragma unroll
    for (int j = 1; j <= 8; ++j)
        wbase += (j > wrp) ? s_btot[j] : 0.0f;      // predicated

    float wa0 = wbase, wa1 = wbase, wa2 = wbase, wa3 = wbase;

    // Edges whose transition can touch this warp's band live in buckets
    // wrp-1 and wrp. tanh saturates naturally -> exact, no window clamp.
    const int bb0 = (wrp > 0) ? (wrp - 1) : 0;
    for (int bb = bb0; bb <= wrp; ++bb) {
        const int cnt = s_bcnt[bb];                 // warp-uniform
        for (int s = 0; s < cnt; ++s) {
            float2 ek = s_bk[bb][s];                // broadcast LDS.64 {w/2, xc/2}
            float hw = ek.x;
            float hu = ek.y - hbf;                  // (xc - x0)/2
            // w * sigmoid(xc - x) = hw * tanh((xc-x)/2) + hw
            float t0, t1, t2, t3;
            asm("tanh.approx.f32 %0, %1;" : "=f"(t0) : "f"(hu));
            asm("tanh.approx.f32 %0, %1;" : "=f"(t1) : "f"(hu - 0.5f));
            asm("tanh.approx.f32 %0, %1;" : "=f"(t2) : "f"(hu - 1.0f));
            asm("tanh.approx.f32 %0, %1;" : "=f"(t3) : "f"(hu - 1.5f));
            wa0 += fmaf(hw, t0, hw);
            wa1 += fmaf(hw, t1, hw);
            wa2 += fmaf(hw, t2, hw);
            wa3 += fmaf(hw, t3, hw);
        }
    }

    // ---- 4. Alpha via tanh.approx + output ----
    float wind[4] = {wa0, wa1, wa2, wa3};
    float4* orow = (float4*)out + (size_t)y * WW + tid * 4;
    #pragma unroll
    for (int q = 0; q < 4; ++q) {
        float th;                                   // sigmoid(4w)=0.5+0.5tanh(2w)
        asm("tanh.approx.f32 %0, %1;" : "=f"(th) : "f"(2.0f * wind[q]));
        float a = fmaf(0.5f, th, 0.5f);
        orow[q] = make_float4(cr, cg, cb, a);
    }
}

extern "C" void kernel_launch(void* const* d_in, const int* in_sizes, int n_in,
                              void* d_out, int out_size)
{
    const float* cp    = (const float*)d_in[0];   // (49, 2) float32
    const float* color = (const float*)d_in[1];   // (3,)   float32
    float* out = (float*)d_out;                   // (1024, 1024, 4) float32
    (void)in_sizes; (void)n_in; (void)out_size;
    bvr_fused_kernel<<<HH, NT>>>(cp, color, out);
}